// round 6
// baseline (speedup 1.0000x reference)
#include <cuda_runtime.h>
#include <cstdint>

typedef unsigned long long u64;

#define DT_F      0.1f
#define NITERS    9               // int(1.0 // 0.1) == 9 in Python float semantics!
#define BATCH     64
#define NN        1024
#define NOBS      64
#define NACT      16
#define GROUPS    4
#define CPB       32              // CTAs per batch
#define BPG       (BATCH / GROUPS)
#define NTHREADS  256

// y-exchange: 8-byte words = (tag<<32) | float_bits; tag = t+1 for y_t. Double buffered.
__device__ u64 g_ybuf[2][BATCH][NN];

__global__ void ctrnn_init_kernel() {
    int i = blockIdx.x * blockDim.x + threadIdx.x;
    if (i < 2 * BATCH * NN) ((u64*)g_ybuf)[i] = 0ull;
}

__device__ __forceinline__ void stcg64(u64* p, u64 v) {
    asm volatile("st.global.cg.u64 [%0], %1;" :: "l"(p), "l"(v) : "memory");
}
// verified v2 global load: spin until both tags == exp
__device__ __forceinline__ void vrfy2g(const u64* p, unsigned exp, u64& a, u64& b) {
    asm volatile("ld.global.cg.v2.u64 {%0,%1}, [%2];" : "=l"(a), "=l"(b) : "l"(p));
    while ((unsigned)(a >> 32) != exp || (unsigned)(b >> 32) != exp) {
        __nanosleep(20);
        asm volatile("ld.global.cg.v2.u64 {%0,%1}, [%2];" : "=l"(a), "=l"(b) : "l"(p));
    }
}
// verified v2 shared load: spin until both stamps match
__device__ __forceinline__ void vrfy2s(uint32_t a, unsigned stamp, u64& x, u64& y) {
    asm volatile("ld.shared.v2.u64 {%0,%1}, [%2];" : "=l"(x), "=l"(y) : "r"(a));
    while ((unsigned)(x >> 32) != stamp || (unsigned)(y >> 32) != stamp) {
        __nanosleep(10);
        asm volatile("ld.shared.v2.u64 {%0,%1}, [%2];" : "=l"(x), "=l"(y) : "r"(a));
    }
}
__device__ __forceinline__ void sts_v2(uint32_t a, u64 x, u64 y) {
    asm volatile("st.shared.v2.u64 [%0], {%1,%2};" :: "r"(a), "l"(x), "l"(y) : "memory");
}

__device__ __forceinline__ void mbar_init(uint32_t a, uint32_t cnt) {
    asm volatile("mbarrier.init.shared.b64 [%0], %1;" :: "r"(a), "r"(cnt) : "memory");
}
__device__ __forceinline__ void mbar_expect_tx(uint32_t a, uint32_t bytes) {
    asm volatile("mbarrier.arrive.expect_tx.shared.b64 _, [%0], %1;" :: "r"(a), "r"(bytes) : "memory");
}
__device__ __forceinline__ void mbar_wait(uint32_t a, uint32_t parity) {
    asm volatile(
        "{\n\t.reg .pred P;\n\t"
        "W_%=:\n\t"
        "mbarrier.try_wait.parity.shared.b64 P, [%0], %1;\n\t"
        "@P bra.uni D_%=;\n\t"
        "bra.uni W_%=;\n\t"
        "D_%=:\n\t}"
        :: "r"(a), "r"(parity) : "memory");
}
__device__ __forceinline__ void bulk_g2s(uint32_t dst, const void* src, uint32_t bytes, uint32_t mbar) {
    asm volatile(
        "cp.async.bulk.shared::cta.global.mbarrier::complete_tx::bytes [%0], [%1], %2, [%3];"
        :: "r"(dst), "l"(src), "r"(bytes), "r"(mbar) : "memory");
}
__device__ __forceinline__ void issue_wload(uint32_t WsAddr, const float* W,
                                            int b, int base, uint32_t mbar) {
    asm volatile("fence.proxy.async.shared::cta;" ::: "memory");
    mbar_expect_tx(mbar, CPB * NN * 4);   // 32 rows * 4KB = 128KB
    const char* src = (const char*)(W + ((size_t)b * NN + base) * NN);
    #pragma unroll
    for (int c = 0; c < 4; c++)
        bulk_g2s(WsAddr + c * 32768, src + c * 32768, 32768, mbar);
}

// SMEM: Ws staging 131072 B | ysm (tagged y, DOUBLE buffered) 2*8192 B | red_s 32 B | mbar 16 B
#define YSM_OFF   131072
#define RED_OFF   (131072 + 16384)
#define MBAR_OFF  (RED_OFF + 32)
#define SMEM_BYTES (MBAR_OFF + 16)

__global__ __launch_bounds__(NTHREADS, 1)
void ctrnn_kernel(const float* __restrict__ obs,  const float* __restrict__ v0,
                  const float* __restrict__ tau,  const float* __restrict__ gain,
                  const float* __restrict__ bias, const float* __restrict__ W,
                  const float* __restrict__ mask, const float* __restrict__ E,
                  const float* __restrict__ D,    float* __restrict__ out)
{
    extern __shared__ char smraw[];
    float4* Ws    = (float4*)smraw;                  // 8192 float4
    u64*    ysm   = (u64*)(smraw + YSM_OFF);         // 2 x 1024 tagged words
    float*  red_s = (float*)(smraw + RED_OFF);       // 8 floats
    u64*    mbar64= (u64*)(smraw + MBAR_OFF);

    const int tid  = threadIdx.x;
    const int warp = tid >> 5;
    const int lane = tid & 31;
    const int group = blockIdx.x >> 5;
    const int cig   = blockIdx.x & 31;
    const int base  = cig * 32;            // first of this CTA's 32 rows

    const uint32_t mbar    = (uint32_t)__cvta_generic_to_shared(mbar64);
    const uint32_t WsAddr  = (uint32_t)__cvta_generic_to_shared(Ws);
    const uint32_t ysmAddr = (uint32_t)__cvta_generic_to_shared(ysm);

    if (tid == 0) {
        mbar_init(mbar, 1);
        asm volatile("fence.proxy.async.shared::cta;" ::: "memory");
    }
    for (int i = tid; i < 2 * NN; i += NTHREADS) ysm[i] = 0ull;   // stamp 0 = invalid
    __syncthreads();
    if (tid == 0) issue_wload(WsAddr, W, group * BPG, base, mbar);

    float4 Wreg[4][8];   // 4 rows x 8 chunks; chunk slot jj holds chunk (warp+jj)&7
    int li = 0;

    for (int bi = 0; bi < BPG; bi++) {
        const int b = group * BPG + bi;

        // ================== prologue (no smem, register-resident params) ==================
        // I = E[n,:] . obs  computed by 8-lane sub-groups (rg = row-in-warp)
        const int rg = lane >> 3;
        const int o0 = (lane & 7) * 8;
        const int nrow = base + warp * 4 + rg;
        const float4* Er = (const float4*)(E + ((size_t)b * NN + nrow) * NOBS + o0);
        const float4* Ob = (const float4*)(obs + (size_t)b * NOBS + o0);
        float4 e0 = Er[0], e1 = Er[1], q0 = Ob[0], q1 = Ob[1];
        float s = e0.x*q0.x + e0.y*q0.y + e0.z*q0.z + e0.w*q0.w
                + e1.x*q1.x + e1.y*q1.y + e1.z*q1.z + e1.w*q1.w;
        s += __shfl_xor_sync(0xffffffffu, s, 1);
        s += __shfl_xor_sync(0xffffffffu, s, 2);
        s += __shfl_xor_sync(0xffffffffu, s, 4);
        float Iv = __shfl_sync(0xffffffffu, s, (lane & 3) * 8);

        // lanes 0..3 own rows base+warp*4+lane; params in registers
        float vv = 0.f, aa = 0.f, gg2 = 0.f, bb2 = 0.f, mm2 = 0.f;
        if (lane < 4) {
            const size_t o = (size_t)b * NN + (base + warp * 4 + lane);
            vv  = v0[o];
            aa  = DT_F / tau[o];
            gg2 = gain[o];
            bb2 = bias[o];
            mm2 = mask[o];
            float y0 = tanhf(gg2 * (vv + bb2)) * mm2;
            stcg64(&g_ybuf[0][b][base + warp * 4 + lane],
                   ((u64)1 << 32) | (u64)__float_as_uint(y0));
        }

        // ---- wait staged W, copy to registers (rotated chunk order) ----
        mbar_wait(mbar, (uint32_t)(li & 1)); li++;
        #pragma unroll
        for (int r = 0; r < 4; r++)
            #pragma unroll
            for (int jj = 0; jj < 8; jj++) {
                int j = (warp + jj) & 7;
                Wreg[r][jj] = Ws[(warp * 4 + r) * 256 + j * 32 + lane];
            }
        __syncthreads();            // staging free for next prefetch
        if (tid == 0 && bi + 1 < BPG)
            issue_wload(WsAddr, W, b + 1, base, mbar);

        // ================== iterations (barrier-free dataflow, dbl-buffered ysm) ==================
        for (int t = 1; t <= NITERS; t++) {
            const u64* src = &g_ybuf[(t - 1) & 1][b][0];
            const unsigned expg  = (unsigned)t;
            const unsigned stamp = (unsigned)(bi * 16 + t);
            const uint32_t ybuf  = ysmAddr + (unsigned)(t & 1) * 8192;

            // produce my chunk (warp w owns y[w*128 .. w*128+127])
            {
                const int i0 = warp * 128 + lane * 4;
                u64 p0, p1, p2, p3;
                vrfy2g(src + i0,     expg, p0, p1);
                vrfy2g(src + i0 + 2, expg, p2, p3);
                const u64 st64 = ((u64)stamp) << 32;
                sts_v2(ybuf + (unsigned)i0 * 8,
                       st64 | (p0 & 0xffffffffu), st64 | (p1 & 0xffffffffu));
                sts_v2(ybuf + (unsigned)i0 * 8 + 16,
                       st64 | (p2 & 0xffffffffu), st64 | (p3 & 0xffffffffu));
            }

            // consume all 8 chunks, starting at my own (rotated)
            float acc0 = 0.f, acc1 = 0.f, acc2 = 0.f, acc3 = 0.f;
            #pragma unroll
            for (int jj = 0; jj < 8; jj++) {
                const int j = (warp + jj) & 7;
                const uint32_t a = ybuf + (unsigned)((j * 128 + lane * 4) * 8);
                u64 x0, x1, x2, x3;
                vrfy2s(a,      stamp, x0, x1);
                vrfy2s(a + 16, stamp, x2, x3);
                const float yx = __uint_as_float((unsigned)x0);
                const float yy = __uint_as_float((unsigned)x1);
                const float yz = __uint_as_float((unsigned)x2);
                const float yw = __uint_as_float((unsigned)x3);
                float4 w;
                w = Wreg[0][jj]; acc0 += w.x*yx; acc0 += w.y*yy; acc0 += w.z*yz; acc0 += w.w*yw;
                w = Wreg[1][jj]; acc1 += w.x*yx; acc1 += w.y*yy; acc1 += w.z*yz; acc1 += w.w*yw;
                w = Wreg[2][jj]; acc2 += w.x*yx; acc2 += w.y*yy; acc2 += w.z*yz; acc2 += w.w*yw;
                w = Wreg[3][jj]; acc3 += w.x*yx; acc3 += w.y*yy; acc3 += w.z*yz; acc3 += w.w*yw;
            }
            #pragma unroll
            for (int off = 16; off > 0; off >>= 1) {
                acc0 += __shfl_xor_sync(0xffffffffu, acc0, off);
                acc1 += __shfl_xor_sync(0xffffffffu, acc1, off);
                acc2 += __shfl_xor_sync(0xffffffffu, acc2, off);
                acc3 += __shfl_xor_sync(0xffffffffu, acc3, off);
            }

            if (lane < 4) {
                float dot = (lane == 0) ? acc0 : (lane == 1) ? acc1
                          : (lane == 2) ? acc2 : acc3;
                float nv = (vv + aa * (dot + Iv - vv)) * mm2;
                vv = nv;
                float ov = (t < NITERS) ? tanhf(gg2 * (nv + bb2)) * mm2 : nv;
                stcg64(&g_ybuf[t & 1][b][base + warp * 4 + lane],
                       ((u64)(unsigned)(t + 1) << 32) | (u64)__float_as_uint(ov));
            }
        }

        // ================== decode: CTAs 0..15 produce one action each ==================
        if (cig < NACT) {
            const u64* srcf = &g_ybuf[NITERS & 1][b][0];
            const int i0 = tid * 4;
            u64 f0, f1, f2, f3;
            vrfy2g(srcf + i0,     (unsigned)(NITERS + 1), f0, f1);
            vrfy2g(srcf + i0 + 2, (unsigned)(NITERS + 1), f2, f3);
            const float4 d4 = *(const float4*)(D + ((size_t)b * NACT + cig) * NN + i0);
            float p = d4.x * __uint_as_float((unsigned)f0)
                    + d4.y * __uint_as_float((unsigned)f1)
                    + d4.z * __uint_as_float((unsigned)f2)
                    + d4.w * __uint_as_float((unsigned)f3);
            #pragma unroll
            for (int off = 16; off > 0; off >>= 1)
                p += __shfl_xor_sync(0xffffffffu, p, off);
            if (lane == 0) red_s[warp] = p;
            __syncthreads();
            if (tid == 0) {
                float sm = 0.f;
                #pragma unroll
                for (int j = 0; j < 8; j++) sm += red_s[j];
                out[b * NACT + cig] = sm;
            }
        }
        // batch-boundary barrier: no warp may start batch bi+1's produce
        // (same ysm parity as bi's last iterations) before all warps finished bi.
        __syncthreads();
    }
}

extern "C" void kernel_launch(void* const* d_in, const int* in_sizes, int n_in,
                              void* d_out, int out_size) {
    const float* obs  = (const float*)d_in[0];
    const float* v0   = (const float*)d_in[1];
    const float* tau  = (const float*)d_in[2];
    const float* gain = (const float*)d_in[3];
    const float* bias = (const float*)d_in[4];
    const float* W    = (const float*)d_in[5];
    const float* mask = (const float*)d_in[6];
    const float* E    = (const float*)d_in[7];
    const float* D    = (const float*)d_in[8];
    float* out = (float*)d_out;

    cudaFuncSetAttribute(ctrnn_kernel,
                         cudaFuncAttributeMaxDynamicSharedMemorySize, SMEM_BYTES);

    // reset exchange tags each launch (required: tag-freshness invariant)
    ctrnn_init_kernel<<<(2 * BATCH * NN + 255) / 256, 256>>>();

    // 128 CTAs, ~144 KB smem each -> 1 CTA/SM, all co-resident
    ctrnn_kernel<<<GROUPS * CPB, NTHREADS, SMEM_BYTES>>>(
        obs, v0, tau, gain, bias, W, mask, E, D, out);
}

// round 7
// speedup vs baseline: 3.8666x; 3.8666x over previous
#include <cuda_runtime.h>
#include <cstdint>

typedef unsigned long long u64;

#define DT_F      0.1f
#define NITERS    9               // int(1.0 // 0.1) == 9 in Python float semantics!
#define BATCH     64
#define NN        1024
#define NOBS      64
#define NACT      16
#define GROUPS    4
#define CPB       32              // CTAs per batch
#define NROWS     32              // rows per CTA
#define BPG       (BATCH / GROUPS)   // 16 batches per group
#define PAIRS     (BPG / 2)          // 8 pairs, interleaved A/B
#define NTHREADS  256

// y-exchange: 8-byte words = (tag<<32)|float_bits; y_t carries tag t+1, lives in buf[t&1].
__device__ u64 g_ybuf[2][BATCH][NN];

__global__ void ctrnn_init_kernel() {
    int i = blockIdx.x * blockDim.x + threadIdx.x;
    if (i < 2 * BATCH * NN) ((u64*)g_ybuf)[i] = 0ull;   // tag 0 = invalid
}

__device__ __forceinline__ u64 ldcg64(const u64* p) {
    u64 v;
    asm volatile("ld.global.cg.u64 %0, [%1];" : "=l"(v) : "l"(p));
    return v;
}
__device__ __forceinline__ void stcg64(u64* p, u64 v) {
    asm volatile("st.global.cg.u64 [%0], %1;" :: "l"(p), "l"(v) : "memory");
}

// issue 4 strided loads (tid, +256, +512, +768) without waiting
__device__ __forceinline__ void prefetch4(const u64* src, int tid, u64 r[4]) {
    r[0] = ldcg64(src + tid);
    r[1] = ldcg64(src + tid + 256);
    r[2] = ldcg64(src + tid + 512);
    r[3] = ldcg64(src + tid + 768);
}
// verify tags (re-poll if stale) and commit to y_s
__device__ __forceinline__ void settle4(const u64* src, unsigned exp, float* y_s,
                                        int tid, u64 r[4]) {
    while ((unsigned)(r[0] >> 32) != exp) { __nanosleep(20); r[0] = ldcg64(src + tid); }
    while ((unsigned)(r[1] >> 32) != exp) { __nanosleep(20); r[1] = ldcg64(src + tid + 256); }
    while ((unsigned)(r[2] >> 32) != exp) { __nanosleep(20); r[2] = ldcg64(src + tid + 512); }
    while ((unsigned)(r[3] >> 32) != exp) { __nanosleep(20); r[3] = ldcg64(src + tid + 768); }
    y_s[tid]       = __uint_as_float((unsigned)(r[0] & 0xffffffffu));
    y_s[tid + 256] = __uint_as_float((unsigned)(r[1] & 0xffffffffu));
    y_s[tid + 512] = __uint_as_float((unsigned)(r[2] & 0xffffffffu));
    y_s[tid + 768] = __uint_as_float((unsigned)(r[3] & 0xffffffffu));
}

__device__ __forceinline__ void mbar_init(uint32_t a, uint32_t cnt) {
    asm volatile("mbarrier.init.shared.b64 [%0], %1;" :: "r"(a), "r"(cnt) : "memory");
}
__device__ __forceinline__ void mbar_expect_tx(uint32_t a, uint32_t bytes) {
    asm volatile("mbarrier.arrive.expect_tx.shared.b64 _, [%0], %1;" :: "r"(a), "r"(bytes) : "memory");
}
__device__ __forceinline__ void mbar_wait(uint32_t a, uint32_t parity) {
    asm volatile(
        "{\n\t.reg .pred P;\n\t"
        "W_%=:\n\t"
        "mbarrier.try_wait.parity.shared.b64 P, [%0], %1;\n\t"
        "@P bra.uni D_%=;\n\t"
        "bra.uni W_%=;\n\t"
        "D_%=:\n\t}"
        :: "r"(a), "r"(parity) : "memory");
}
__device__ __forceinline__ void bulk_g2s(uint32_t dst, const void* src, uint32_t bytes, uint32_t mbar) {
    asm volatile(
        "cp.async.bulk.shared::cta.global.mbarrier::complete_tx::bytes [%0], [%1], %2, [%3];"
        :: "r"(dst), "l"(src), "r"(bytes), "r"(mbar) : "memory");
}
__device__ __forceinline__ void issue_wload(uint32_t WsAddr, const float* W,
                                            int b, int base, uint32_t mbar) {
    asm volatile("fence.proxy.async.shared::cta;" ::: "memory");
    mbar_expect_tx(mbar, NROWS * NN * 4);
    const char* src = (const char*)(W + ((size_t)b * NN + base) * NN);
    #pragma unroll
    for (int c = 0; c < 4; c++)
        bulk_g2s(WsAddr + c * 32768, src + c * 32768, 32768, mbar);
}

// SMEM: Ws staging 131072 | y_sA 4096 | y_sB 4096 | PA 768 | PB 768 | obs 256 | red 32 | mbar 16
#define SMEM_FLOATS (NROWS * NN + 2 * NN + 12 * NROWS + NOBS + 8 + 4)
#define SMEM_BYTES  (SMEM_FLOATS * 4)

// prologue: obs -> smem, params -> P, publish y0 (tag 1) for own rows
__device__ __forceinline__ void prologue(int b, int base, int tid,
    const float* __restrict__ obs, const float* __restrict__ v0,
    const float* __restrict__ tau, const float* __restrict__ gain,
    const float* __restrict__ bias, const float* __restrict__ mask,
    const float* __restrict__ E, float* P, float* obs_s)
{
    if (tid < NOBS) obs_s[tid] = obs[(size_t)b * NOBS + tid];
    __syncthreads();
    if (tid < NROWS) {
        int n = base + tid;
        const size_t o = (size_t)b * NN + n;
        float vv = v0[o], gg = gain[o], bb = bias[o], mm = mask[o];
        P[0 * NROWS + tid] = vv;
        P[1 * NROWS + tid] = DT_F / tau[o];
        P[3 * NROWS + tid] = gg;
        P[4 * NROWS + tid] = bb;
        P[5 * NROWS + tid] = mm;
        const float* Er = E + o * NOBS;
        float s = 0.f;
        #pragma unroll
        for (int q = 0; q < NOBS; q++) s += Er[q] * obs_s[q];
        P[2 * NROWS + tid] = s;
        float y0 = tanhf(gg * (vv + bb)) * mm;
        stcg64(&g_ybuf[0][b][n], ((u64)1 << 32) | (u64)__float_as_uint(y0));
    }
    __syncthreads();   // obs_s free for next prologue
}

// decode: CTA cig (<NACT) produces action cig of batch b
__device__ __forceinline__ void decode(int b, int cig, int tid, int warp, int lane,
                                       const float* __restrict__ D, float* out,
                                       float* y_stage, float* red_s)
{
    u64 r[4];
    const u64* src = &g_ybuf[NITERS & 1][b][0];
    prefetch4(src, tid, r);
    settle4(src, (unsigned)(NITERS + 1), y_stage, tid, r);
    __syncthreads();
    const float* Dr = D + ((size_t)b * NACT + cig) * NN;
    float p = 0.f;
    for (int i = tid; i < NN; i += NTHREADS) p += Dr[i] * y_stage[i];
    #pragma unroll
    for (int off = 16; off > 0; off >>= 1)
        p += __shfl_xor_sync(0xffffffffu, p, off);
    if (lane == 0) red_s[warp] = p;
    __syncthreads();
    if (tid == 0) {
        float s = 0.f;
        #pragma unroll
        for (int j = 0; j < 8; j++) s += red_s[j];
        out[b * NACT + cig] = s;
    }
    __syncthreads();
}

__global__ __launch_bounds__(NTHREADS, 1)
void ctrnn_kernel(const float* __restrict__ obs,  const float* __restrict__ v0,
                  const float* __restrict__ tau,  const float* __restrict__ gain,
                  const float* __restrict__ bias, const float* __restrict__ W,
                  const float* __restrict__ mask, const float* __restrict__ E,
                  const float* __restrict__ D,    float* __restrict__ out)
{
    extern __shared__ float4 sm4[];
    float4* Ws    = sm4;                               // 8192 float4
    float*  y_sA  = (float*)(Ws + NROWS * (NN / 4));   // 1024
    float*  y_sB  = y_sA + NN;                         // 1024
    float*  PA    = y_sB + NN;                         // 6*32
    float*  PB    = PA + 6 * NROWS;                    // 6*32
    float*  obs_s = PB + 6 * NROWS;                    // 64
    float*  red_s = obs_s + NOBS;                      // 8
    u64*    mbar64 = (u64*)(red_s + 8);

    const int tid  = threadIdx.x;
    const int warp = tid >> 5;
    const int lane = tid & 31;
    const int group = blockIdx.x >> 5;
    const int cig   = blockIdx.x & 31;
    const int base  = cig * NROWS;

    const uint32_t mbar   = (uint32_t)__cvta_generic_to_shared(mbar64);
    const uint32_t WsAddr = (uint32_t)__cvta_generic_to_shared(Ws);

    if (tid == 0) {
        mbar_init(mbar, 1);
        asm volatile("fence.proxy.async.shared::cta;" ::: "memory");
        issue_wload(WsAddr, W, group * BPG + 0, base, mbar);
    }
    __syncthreads();

    float4 Wreg[4][8];
    int li = 0;
    u64 pa[4], pb[4];

    for (int p = 0; p < PAIRS; p++) {
        const int bA = group * BPG + 2 * p;
        const int bB = bA + 1;

        // ---- wait W_A, copy staging -> registers ----
        mbar_wait(mbar, (uint32_t)(li & 1)); li++;
        {
            const float4* Wrow0 = Ws + (size_t)(warp * 4) * (NN / 4);
            #pragma unroll
            for (int r = 0; r < 4; r++)
                #pragma unroll
                for (int j = 0; j < 8; j++)
                    Wreg[r][j] = Wrow0[r * (NN / 4) + j * 32 + lane];
        }
        __syncthreads();   // staging free

        // ---- issue W_B into staging (resident for the whole pair) ----
        if (tid == 0) issue_wload(WsAddr, W, bB, base, mbar);

        // ---- lightweight prologues (overlap W_B flight); publish y0 with tag 1 ----
        prologue(bA, base, tid, obs, v0, tau, gain, bias, mask, E, PA, obs_s);
        prologue(bB, base, tid, obs, v0, tau, gain, bias, mask, E, PB, obs_s);

        // initial prefetches: y0 of both batches (tag 1, buf 0)
        prefetch4(&g_ybuf[0][bA][0], tid, pa);
        prefetch4(&g_ybuf[0][bB][0], tid, pb);

        mbar_wait(mbar, (uint32_t)(li & 1)); li++;   // W_B resident
        __syncthreads();

        const float4* Y4A = (const float4*)y_sA;
        const float4* Y4B = (const float4*)y_sB;

        for (int t = 1; t <= NITERS; t++) {
            // ============ batch A phase (W in registers) ============
            settle4(&g_ybuf[(t - 1) & 1][bA][0], (unsigned)t, y_sA, tid, pa);
            __syncthreads();
            {
                float acc0 = 0.f, acc1 = 0.f, acc2 = 0.f, acc3 = 0.f;
                #pragma unroll
                for (int j = 0; j < 8; j++) {
                    float4 y4 = Y4A[j * 32 + lane];
                    float4 a;
                    a = Wreg[0][j]; acc0 += a.x*y4.x; acc0 += a.y*y4.y; acc0 += a.z*y4.z; acc0 += a.w*y4.w;
                    a = Wreg[1][j]; acc1 += a.x*y4.x; acc1 += a.y*y4.y; acc1 += a.z*y4.z; acc1 += a.w*y4.w;
                    a = Wreg[2][j]; acc2 += a.x*y4.x; acc2 += a.y*y4.y; acc2 += a.z*y4.z; acc2 += a.w*y4.w;
                    a = Wreg[3][j]; acc3 += a.x*y4.x; acc3 += a.y*y4.y; acc3 += a.z*y4.z; acc3 += a.w*y4.w;
                }
                #pragma unroll
                for (int off = 16; off > 0; off >>= 1) {
                    acc0 += __shfl_xor_sync(0xffffffffu, acc0, off);
                    acc1 += __shfl_xor_sync(0xffffffffu, acc1, off);
                    acc2 += __shfl_xor_sync(0xffffffffu, acc2, off);
                    acc3 += __shfl_xor_sync(0xffffffffu, acc3, off);
                }
                if (lane < 4) {
                    float dot = (lane == 0) ? acc0 : (lane == 1) ? acc1 : (lane == 2) ? acc2 : acc3;
                    int r = warp * 4 + lane;
                    float v  = PA[0 * NROWS + r];
                    float nv = (v + PA[1 * NROWS + r] * (dot + PA[2 * NROWS + r] - v)) * PA[5 * NROWS + r];
                    PA[0 * NROWS + r] = nv;
                    float ov = (t < NITERS)
                        ? tanhf(PA[3 * NROWS + r] * (nv + PA[4 * NROWS + r])) * PA[5 * NROWS + r]
                        : nv;
                    stcg64(&g_ybuf[t & 1][bA][base + r],
                           ((u64)(unsigned)(t + 1) << 32) | (u64)__float_as_uint(ov));
                }
            }
            // issue next A gather early: y_A(t) (tag t+1) lands during B phase
            if (t < NITERS) prefetch4(&g_ybuf[t & 1][bA][0], tid, pa);

            // ============ batch B phase (W in SMEM) ============
            settle4(&g_ybuf[(t - 1) & 1][bB][0], (unsigned)t, y_sB, tid, pb);
            __syncthreads();
            {
                float acc0 = 0.f, acc1 = 0.f, acc2 = 0.f, acc3 = 0.f;
                const float4* W0 = Ws + (size_t)(warp * 4 + 0) * (NN / 4);
                const float4* W1 = W0 + (NN / 4);
                const float4* W2 = W1 + (NN / 4);
                const float4* W3 = W2 + (NN / 4);
                #pragma unroll
                for (int k = 0; k < 8; k++) {
                    int c = k * 32 + lane;
                    float4 y4 = Y4B[c];
                    float4 a;
                    a = W0[c]; acc0 += a.x*y4.x; acc0 += a.y*y4.y; acc0 += a.z*y4.z; acc0 += a.w*y4.w;
                    a = W1[c]; acc1 += a.x*y4.x; acc1 += a.y*y4.y; acc1 += a.z*y4.z; acc1 += a.w*y4.w;
                    a = W2[c]; acc2 += a.x*y4.x; acc2 += a.y*y4.y; acc2 += a.z*y4.z; acc2 += a.w*y4.w;
                    a = W3[c]; acc3 += a.x*y4.x; acc3 += a.y*y4.y; acc3 += a.z*y4.z; acc3 += a.w*y4.w;
                }
                #pragma unroll
                for (int off = 16; off > 0; off >>= 1) {
                    acc0 += __shfl_xor_sync(0xffffffffu, acc0, off);
                    acc1 += __shfl_xor_sync(0xffffffffu, acc1, off);
                    acc2 += __shfl_xor_sync(0xffffffffu, acc2, off);
                    acc3 += __shfl_xor_sync(0xffffffffu, acc3, off);
                }
                if (lane < 4) {
                    float dot = (lane == 0) ? acc0 : (lane == 1) ? acc1 : (lane == 2) ? acc2 : acc3;
                    int r = warp * 4 + lane;
                    float v  = PB[0 * NROWS + r];
                    float nv = (v + PB[1 * NROWS + r] * (dot + PB[2 * NROWS + r] - v)) * PB[5 * NROWS + r];
                    PB[0 * NROWS + r] = nv;
                    float ov = (t < NITERS)
                        ? tanhf(PB[3 * NROWS + r] * (nv + PB[4 * NROWS + r])) * PB[5 * NROWS + r]
                        : nv;
                    stcg64(&g_ybuf[t & 1][bB][base + r],
                           ((u64)(unsigned)(t + 1) << 32) | (u64)__float_as_uint(ov));
                }
            }
            // issue next B gather early: settles after next A phase
            if (t < NITERS) prefetch4(&g_ybuf[t & 1][bB][0], tid, pb);
        }
        __syncthreads();   // done with Ws (W_B) and y buffers

        // ---- prefetch next pair's W_A into staging (overlaps decode) ----
        if (tid == 0 && p + 1 < PAIRS) issue_wload(WsAddr, W, bA + 2, base, mbar);

        // ---- decode: CTAs 0..15 produce one action each for both batches ----
        if (cig < NACT) {
            decode(bA, cig, tid, warp, lane, D, out, y_sA, red_s);
            decode(bB, cig, tid, warp, lane, D, out, y_sA, red_s);
        }
        __syncthreads();
    }
}

extern "C" void kernel_launch(void* const* d_in, const int* in_sizes, int n_in,
                              void* d_out, int out_size) {
    const float* obs  = (const float*)d_in[0];
    const float* v0   = (const float*)d_in[1];
    const float* tau  = (const float*)d_in[2];
    const float* gain = (const float*)d_in[3];
    const float* bias = (const float*)d_in[4];
    const float* W    = (const float*)d_in[5];
    const float* mask = (const float*)d_in[6];
    const float* E    = (const float*)d_in[7];
    const float* D    = (const float*)d_in[8];
    float* out = (float*)d_out;

    cudaFuncSetAttribute(ctrnn_kernel,
                         cudaFuncAttributeMaxDynamicSharedMemorySize, SMEM_BYTES);

    // reset exchange tags each launch (tag-freshness invariant, graph-replay safe)
    ctrnn_init_kernel<<<(2 * BATCH * NN + 255) / 256, 256>>>();

    // 128 CTAs, ~141 KB smem each -> 1 CTA/SM, all co-resident
    ctrnn_kernel<<<GROUPS * CPB, NTHREADS, SMEM_BYTES>>>(
        obs, v0, tau, gain, bias, W, mask, E, D, out);
}

// round 8
// speedup vs baseline: 5.2468x; 1.3569x over previous
#include <cuda_runtime.h>
#include <cstdint>

typedef unsigned long long u64;

#define DT_F      0.1f
#define NITERS    9               // int(1.0 // 0.1) == 9 in Python float semantics!
#define BATCH     64
#define NN        1024
#define NOBS      64
#define NACT      16
#define GROUPS    8               // groups of 16 CTAs; one batch at a time per group
#define CPB       16              // CTAs per batch
#define ROWS_CTA  64              // rows per CTA (32 in regs + 32 in smem)
#define BPG       (BATCH / GROUPS)   // 8 batches per group
#define NTHREADS  256

// y-exchange: 8-byte words = (tag<<32)|float_bits; y_t carries tag t+1, in buf[t&1].
__device__ u64 g_ybuf[2][BATCH][NN];

__global__ void ctrnn_init_kernel() {
    int i = blockIdx.x * blockDim.x + threadIdx.x;
    if (i < 2 * BATCH * NN) ((u64*)g_ybuf)[i] = 0ull;   // tag 0 = invalid
}

__device__ __forceinline__ u64 ldcg64(const u64* p) {
    u64 v;
    asm volatile("ld.global.cg.u64 %0, [%1];" : "=l"(v) : "l"(p));
    return v;
}
__device__ __forceinline__ void stcg64(u64* p, u64 v) {
    asm volatile("st.global.cg.u64 [%0], %1;" :: "l"(p), "l"(v) : "memory");
}

// gather 1024 tagged words (4 per thread, strided 256), spin until tag==exp
__device__ __forceinline__ void settle4(const u64* src, unsigned exp, float* y_s, int tid) {
    u64 r0 = ldcg64(src + tid);
    u64 r1 = ldcg64(src + tid + 256);
    u64 r2 = ldcg64(src + tid + 512);
    u64 r3 = ldcg64(src + tid + 768);
    while ((unsigned)(r0 >> 32) != exp) { __nanosleep(20); r0 = ldcg64(src + tid); }
    while ((unsigned)(r1 >> 32) != exp) { __nanosleep(20); r1 = ldcg64(src + tid + 256); }
    while ((unsigned)(r2 >> 32) != exp) { __nanosleep(20); r2 = ldcg64(src + tid + 512); }
    while ((unsigned)(r3 >> 32) != exp) { __nanosleep(20); r3 = ldcg64(src + tid + 768); }
    y_s[tid]       = __uint_as_float((unsigned)(r0 & 0xffffffffu));
    y_s[tid + 256] = __uint_as_float((unsigned)(r1 & 0xffffffffu));
    y_s[tid + 512] = __uint_as_float((unsigned)(r2 & 0xffffffffu));
    y_s[tid + 768] = __uint_as_float((unsigned)(r3 & 0xffffffffu));
}

__device__ __forceinline__ void mbar_init(uint32_t a, uint32_t cnt) {
    asm volatile("mbarrier.init.shared.b64 [%0], %1;" :: "r"(a), "r"(cnt) : "memory");
}
__device__ __forceinline__ void mbar_expect_tx(uint32_t a, uint32_t bytes) {
    asm volatile("mbarrier.arrive.expect_tx.shared.b64 _, [%0], %1;" :: "r"(a), "r"(bytes) : "memory");
}
__device__ __forceinline__ void mbar_wait(uint32_t a, uint32_t parity) {
    asm volatile(
        "{\n\t.reg .pred P;\n\t"
        "W_%=:\n\t"
        "mbarrier.try_wait.parity.shared.b64 P, [%0], %1;\n\t"
        "@P bra.uni D_%=;\n\t"
        "bra.uni W_%=;\n\t"
        "D_%=:\n\t}"
        :: "r"(a), "r"(parity) : "memory");
}
__device__ __forceinline__ void bulk_g2s(uint32_t dst, const void* src, uint32_t bytes, uint32_t mbar) {
    asm volatile(
        "cp.async.bulk.shared::cta.global.mbarrier::complete_tx::bytes [%0], [%1], %2, [%3];"
        :: "r"(dst), "l"(src), "r"(bytes), "r"(mbar) : "memory");
}
// issue `bytes` (multiple of 32KB) from gsrc into smem dst, completing on mbar
__device__ __forceinline__ void issue_chunks(uint32_t dst, const char* gsrc,
                                             uint32_t bytes, uint32_t mbar) {
    asm volatile("fence.proxy.async.shared::cta;" ::: "memory");
    mbar_expect_tx(mbar, bytes);
    for (uint32_t c = 0; c < bytes; c += 32768)
        bulk_g2s(dst + c, gsrc + c, 32768, mbar);
}

// SMEM layout (bytes):
//   S1 (smem W half, 32 rows)   : [0, 131072)
//   S0 (staging, 16 rows)       : [131072, 196608)
//   y_s[2][1024]                : [196608, 204800)
//   P[6][64]                    : [204800, 206336)
//   obs_s[64]                   : [206336, 206592)
//   red_s[8]                    : [206592, 206624)
//   mbar0, mbar1                : [206624, 206640)
#define S1_OFF    0
#define S0_OFF    131072
#define YS_OFF    196608
#define P_OFF     204800
#define OBS_OFF   206336
#define RED_OFF   206592
#define MB_OFF    206624
#define SMEM_BYTES 206640

__global__ __launch_bounds__(NTHREADS, 1)
void ctrnn_kernel(const float* __restrict__ obs,  const float* __restrict__ v0,
                  const float* __restrict__ tau,  const float* __restrict__ gain,
                  const float* __restrict__ bias, const float* __restrict__ W,
                  const float* __restrict__ mask, const float* __restrict__ E,
                  const float* __restrict__ D,    float* __restrict__ out)
{
    extern __shared__ char sm[];
    float4* S1f4  = (float4*)(sm + S1_OFF);    // 32 rows x 256 float4
    float4* S0f4  = (float4*)(sm + S0_OFF);    // 16 rows x 256 float4
    float*  y_s0  = (float*)(sm + YS_OFF);     // parity 0
    float*  y_s1  = y_s0 + NN;                 // parity 1
    float*  P     = (float*)(sm + P_OFF);      // [6][64]
    float*  obs_s = (float*)(sm + OBS_OFF);
    float*  red_s = (float*)(sm + RED_OFF);
    u64*    mb    = (u64*)(sm + MB_OFF);

    const int tid  = threadIdx.x;
    const int warp = tid >> 5;
    const int lane = tid & 31;
    const int group = blockIdx.x >> 4;        // /16
    const int cig   = blockIdx.x & 15;
    const int base  = cig * ROWS_CTA;         // first of this CTA's 64 rows

    const uint32_t mbar0 = (uint32_t)__cvta_generic_to_shared(mb);
    const uint32_t mbar1 = mbar0 + 8;
    const uint32_t S0a   = (uint32_t)__cvta_generic_to_shared(S0f4);
    const uint32_t S1a   = (uint32_t)__cvta_generic_to_shared(S1f4);

    if (tid == 0) {
        mbar_init(mbar0, 1);
        mbar_init(mbar1, 1);
        asm volatile("fence.proxy.async.shared::cta;" ::: "memory");
    }
    __syncthreads();

    // W chunk of batch b starts at W + (b*NN + base)*NN  (64 rows x 4KB = 256KB)
    //   part1 (rows 0-15, 64KB) -> S0 ; part2 (rows 16-31, 64KB) -> S0 ; smem half (rows 32-63, 128KB) -> S1
    if (tid == 0) {
        const char* g = (const char*)(W + ((size_t)(group * BPG) * NN + base) * NN);
        issue_chunks(S0a, g, 65536, mbar0);          // part1 of batch 0
    }

    float4 Wreg[4][8];   // this warp's 4 register rows x 8 float4-chunks
    int li0 = 0, li1 = 0;

    for (int bi = 0; bi < BPG; bi++) {
        const int b = group * BPG + bi;
        const char* gW = (const char*)(W + ((size_t)b * NN + base) * NN);

        // ---------- batch start: assemble W ----------
        mbar_wait(mbar0, (uint32_t)(li0 & 1)); li0++;        // part1 in S0
        if (warp < 4) {   // warps 0-3 own reg rows 0-15
            #pragma unroll
            for (int r = 0; r < 4; r++)
                #pragma unroll
                for (int j = 0; j < 8; j++)
                    Wreg[r][j] = S0f4[(warp * 4 + r) * 256 + j * 32 + lane];
        }
        __syncthreads();                                     // S0 free
        if (tid == 0) {
            issue_chunks(S0a, gW + 65536, 65536, mbar0);     // part2
            issue_chunks(S1a, gW + 131072, 131072, mbar1);   // smem half
        }

        // ---------- prologue (overlaps TMA) ----------
        if (tid < NOBS) obs_s[tid] = obs[(size_t)b * NOBS + tid];
        __syncthreads();
        if (tid < ROWS_CTA) {
            const int n = base + tid;
            const size_t o = (size_t)b * NN + n;
            float vv = v0[o], gg = gain[o], bb = bias[o], mm = mask[o];
            P[0 * 64 + tid] = vv;
            P[1 * 64 + tid] = DT_F / tau[o];
            P[3 * 64 + tid] = gg;
            P[4 * 64 + tid] = bb;
            P[5 * 64 + tid] = mm;
            const float* Er = E + o * NOBS;
            float s = 0.f;
            #pragma unroll
            for (int q = 0; q < NOBS; q++) s += Er[q] * obs_s[q];
            P[2 * 64 + tid] = s;
            float y0 = tanhf(gg * (vv + bb)) * mm;
            stcg64(&g_ybuf[0][b][n], ((u64)1 << 32) | (u64)__float_as_uint(y0));
        }

        mbar_wait(mbar0, (uint32_t)(li0 & 1)); li0++;        // part2 in S0
        if (warp >= 4) {  // warps 4-7 own reg rows 16-31
            #pragma unroll
            for (int r = 0; r < 4; r++)
                #pragma unroll
                for (int j = 0; j < 8; j++)
                    Wreg[r][j] = S0f4[((warp - 4) * 4 + r) * 256 + j * 32 + lane];
        }
        mbar_wait(mbar1, (uint32_t)(li1 & 1)); li1++;        // smem half in S1
        __syncthreads();                                     // S0 free, S1 + P ready
        if (tid == 0 && bi + 1 < BPG) {
            const char* gn = (const char*)(W + ((size_t)(b + 1) * NN + base) * NN);
            issue_chunks(S0a, gn, 65536, mbar0);             // next part1, flies during iters
        }

        // ---------- iterations ----------
        const float4* S1w = S1f4 + (size_t)(warp * 4) * 256; // this warp's 4 smem rows
        for (int t = 1; t <= NITERS; t++) {
            float* ys = (t & 1) ? y_s1 : y_s0;
            settle4(&g_ybuf[(t - 1) & 1][b][0], (unsigned)t, ys, tid);
            __syncthreads();
            const float4* Y4 = (const float4*)ys;

            float ar0 = 0.f, ar1 = 0.f, ar2 = 0.f, ar3 = 0.f;
            float as0 = 0.f, as1 = 0.f, as2 = 0.f, as3 = 0.f;
            #pragma unroll
            for (int j = 0; j < 8; j++) {
                const float4 y4 = Y4[j * 32 + lane];
                float4 w;
                w = Wreg[0][j];           ar0 += w.x*y4.x; ar0 += w.y*y4.y; ar0 += w.z*y4.z; ar0 += w.w*y4.w;
                w = Wreg[1][j];           ar1 += w.x*y4.x; ar1 += w.y*y4.y; ar1 += w.z*y4.z; ar1 += w.w*y4.w;
                w = Wreg[2][j];           ar2 += w.x*y4.x; ar2 += w.y*y4.y; ar2 += w.z*y4.z; ar2 += w.w*y4.w;
                w = Wreg[3][j];           ar3 += w.x*y4.x; ar3 += w.y*y4.y; ar3 += w.z*y4.z; ar3 += w.w*y4.w;
                w = S1w[0 * 256 + j * 32 + lane]; as0 += w.x*y4.x; as0 += w.y*y4.y; as0 += w.z*y4.z; as0 += w.w*y4.w;
                w = S1w[1 * 256 + j * 32 + lane]; as1 += w.x*y4.x; as1 += w.y*y4.y; as1 += w.z*y4.z; as1 += w.w*y4.w;
                w = S1w[2 * 256 + j * 32 + lane]; as2 += w.x*y4.x; as2 += w.y*y4.y; as2 += w.z*y4.z; as2 += w.w*y4.w;
                w = S1w[3 * 256 + j * 32 + lane]; as3 += w.x*y4.x; as3 += w.y*y4.y; as3 += w.z*y4.z; as3 += w.w*y4.w;
            }
            #pragma unroll
            for (int off = 16; off > 0; off >>= 1) {
                ar0 += __shfl_xor_sync(0xffffffffu, ar0, off);
                ar1 += __shfl_xor_sync(0xffffffffu, ar1, off);
                ar2 += __shfl_xor_sync(0xffffffffu, ar2, off);
                ar3 += __shfl_xor_sync(0xffffffffu, ar3, off);
                as0 += __shfl_xor_sync(0xffffffffu, as0, off);
                as1 += __shfl_xor_sync(0xffffffffu, as1, off);
                as2 += __shfl_xor_sync(0xffffffffu, as2, off);
                as3 += __shfl_xor_sync(0xffffffffu, as3, off);
            }

            if (lane < 8) {
                float dot;
                int rloc;
                if (lane < 4) {
                    dot  = (lane == 0) ? ar0 : (lane == 1) ? ar1 : (lane == 2) ? ar2 : ar3;
                    rloc = warp * 4 + lane;
                } else {
                    dot  = (lane == 4) ? as0 : (lane == 5) ? as1 : (lane == 6) ? as2 : as3;
                    rloc = 32 + warp * 4 + (lane - 4);
                }
                float v  = P[0 * 64 + rloc];
                float nv = (v + P[1 * 64 + rloc] * (dot + P[2 * 64 + rloc] - v)) * P[5 * 64 + rloc];
                P[0 * 64 + rloc] = nv;
                float ov = (t < NITERS)
                    ? tanhf(P[3 * 64 + rloc] * (nv + P[4 * 64 + rloc])) * P[5 * 64 + rloc]
                    : nv;
                stcg64(&g_ybuf[t & 1][b][base + rloc],
                       ((u64)(unsigned)(t + 1) << 32) | (u64)__float_as_uint(ov));
            }
        }

        // ---------- decode: every CTA produces one action ----------
        // safe: a warp reaches here only after compute(9); all warps passed sync(9)
        // (pre-compute barrier of t=9), so nobody still reads y_s0 (last read was t=8).
        settle4(&g_ybuf[NITERS & 1][b][0], (unsigned)(NITERS + 1), y_s0, tid);
        __syncthreads();
        {
            const float* Dr = D + ((size_t)b * NACT + cig) * NN;
            float p = 0.f;
            for (int i = tid; i < NN; i += NTHREADS) p += Dr[i] * y_s0[i];
            #pragma unroll
            for (int off = 16; off > 0; off >>= 1)
                p += __shfl_xor_sync(0xffffffffu, p, off);
            if (lane == 0) red_s[warp] = p;
            __syncthreads();
            if (tid == 0) {
                float s = 0.f;
                #pragma unroll
                for (int j = 0; j < 8; j++) s += red_s[j];
                out[b * NACT + cig] = s;
            }
        }
        __syncthreads();   // y_s0 / red_s / P free for next batch
    }
}

extern "C" void kernel_launch(void* const* d_in, const int* in_sizes, int n_in,
                              void* d_out, int out_size) {
    const float* obs  = (const float*)d_in[0];
    const float* v0   = (const float*)d_in[1];
    const float* tau  = (const float*)d_in[2];
    const float* gain = (const float*)d_in[3];
    const float* bias = (const float*)d_in[4];
    const float* W    = (const float*)d_in[5];
    const float* mask = (const float*)d_in[6];
    const float* E    = (const float*)d_in[7];
    const float* D    = (const float*)d_in[8];
    float* out = (float*)d_out;

    cudaFuncSetAttribute(ctrnn_kernel,
                         cudaFuncAttributeMaxDynamicSharedMemorySize, SMEM_BYTES);

    // reset exchange tags each launch (tag-freshness invariant, graph-replay safe)
    ctrnn_init_kernel<<<(2 * BATCH * NN + 255) / 256, 256>>>();

    // 128 CTAs = 8 groups x 16; ~202 KB smem each -> 1 CTA/SM, all co-resident
    ctrnn_kernel<<<GROUPS * CPB, NTHREADS, SMEM_BYTES>>>(
        obs, v0, tau, gain, bias, W, mask, E, D, out);
}